// round 17
// baseline (speedup 1.0000x reference)
#include <cuda_runtime.h>
#include <cuda_bf16.h>
#include <cstdint>

// Problem constants
#define S  4096
#define D  512
#define H  8
#define DK 64
#define FF 2048
#define EPS 1e-6f

// ---------------- scratch (device globals; no allocation allowed) ----------------
__device__ float g_x1[S * D];
__device__ __nv_bfloat16 g_hb  [S * D];
__device__ __nv_bfloat16 g_h2b [S * D];
__device__ __nv_bfloat16 g_attnb[S * D];
__device__ __nv_bfloat16 g_ffb [S * FF];
__device__ __nv_bfloat16 g_qb[S * D];
__device__ __nv_bfloat16 g_kb[S * D];
__device__ __nv_bfloat16 g_vb[S * D];
__device__ __nv_bfloat16 g_wqt[D * D];
__device__ __nv_bfloat16 g_wkt[D * D];
__device__ __nv_bfloat16 g_wvt[D * D];
__device__ __nv_bfloat16 g_wot[D * D];
__device__ __nv_bfloat16 g_w1t[FF * D];
__device__ __nv_bfloat16 g_w2t[D * FF];

// ---------------- helpers ----------------
__device__ __forceinline__ uint32_t packbf(float lo, float hi) {
    uint32_t r;
    asm("cvt.rn.bf16x2.f32 %0, %1, %2;" : "=r"(r) : "f"(hi), "f"(lo));
    return r;
}

__device__ __forceinline__ float ex2(float x) {
    float r;
    asm("ex2.approx.f32 %0, %1;" : "=f"(r) : "f"(x));
    return r;
}

__device__ __forceinline__ void mma_bf16(float* c, const uint32_t* a, uint32_t b0, uint32_t b1) {
    asm volatile(
        "mma.sync.aligned.m16n8k16.row.col.f32.bf16.bf16.f32 "
        "{%0,%1,%2,%3},{%4,%5,%6,%7},{%8,%9},{%0,%1,%2,%3};"
        : "+f"(c[0]), "+f"(c[1]), "+f"(c[2]), "+f"(c[3])
        : "r"(a[0]), "r"(a[1]), "r"(a[2]), "r"(a[3]), "r"(b0), "r"(b1));
}

__device__ __forceinline__ void cpa16(void* dst, const void* src) {
    uint32_t d = (uint32_t)__cvta_generic_to_shared(dst);
    asm volatile("cp.async.ca.shared.global [%0], [%1], 16;" :: "r"(d), "l"(src));
}
#define CP_COMMIT() asm volatile("cp.async.commit_group;")
#define CP_WAIT1()  asm volatile("cp.async.wait_group 1;")

__device__ __forceinline__ void ldsm_x2(uint32_t& r0, uint32_t& r1, uint32_t a) {
    asm volatile("ldmatrix.sync.aligned.m8n8.x2.shared.b16 {%0,%1}, [%2];"
                 : "=r"(r0), "=r"(r1) : "r"(a));
}
__device__ __forceinline__ void ldsm_x2_t(uint32_t& r0, uint32_t& r1, uint32_t a) {
    asm volatile("ldmatrix.sync.aligned.m8n8.x2.trans.shared.b16 {%0,%1}, [%2];"
                 : "=r"(r0), "=r"(r1) : "r"(a));
}
__device__ __forceinline__ void ldsm_x4(uint32_t* r, uint32_t a) {
    asm volatile("ldmatrix.sync.aligned.m8n8.x4.shared.b16 {%0,%1,%2,%3}, [%4];"
                 : "=r"(r[0]), "=r"(r[1]), "=r"(r[2]), "=r"(r[3]) : "r"(a));
}
__device__ __forceinline__ void ldsm_x4_t(uint32_t* r, uint32_t a) {
    asm volatile("ldmatrix.sync.aligned.m8n8.x4.trans.shared.b16 {%0,%1,%2,%3}, [%4];"
                 : "=r"(r[0]), "=r"(r[1]), "=r"(r[2]), "=r"(r[3]) : "r"(a));
}

extern __shared__ char sm_raw[];

__device__ __forceinline__ float block_sum(float v) {
    __shared__ float sh[8];
    #pragma unroll
    for (int o = 16; o > 0; o >>= 1) v += __shfl_xor_sync(0xffffffffu, v, o);
    if ((threadIdx.x & 31) == 0) sh[threadIdx.x >> 5] = v;
    __syncthreads();
    if (threadIdx.x < 32) {
        float t = (threadIdx.x < 8) ? sh[threadIdx.x] : 0.f;
        #pragma unroll
        for (int o = 4; o > 0; o >>= 1) t += __shfl_xor_sync(0xffffffffu, t, o);
        if (threadIdx.x == 0) sh[0] = t;
    }
    __syncthreads();
    float r = sh[0];
    __syncthreads();
    return r;
}

// ---------------- LayerNorm body (torch.std semantics), bf16 output ----------------
__device__ __forceinline__ void ln_row(
    const float* __restrict__ x, __nv_bfloat16* __restrict__ y, int row,
    const float* __restrict__ alpha, const float* __restrict__ beta)
{
    const float* xr = x + (size_t)row * D;
    float s = 0.f;
    for (int i = threadIdx.x; i < D; i += 256) s += xr[i];
    float mean = block_sum(s) * (1.0f / D);

    float sq = 0.f;
    for (int i = threadIdx.x; i < D; i += 256) {
        float d = xr[i] - mean;
        sq += d * d;
    }
    float var = block_sum(sq) * (1.0f / (D - 1));
    float stdv = sqrtf(var);
    float a = alpha[0], b = beta[0];
    float inv = a / (stdv + EPS);
    __nv_bfloat16* yr = y + (size_t)row * D;
    for (int i = threadIdx.x; i < D; i += 256)
        yr[i] = __float2bfloat16((xr[i] - mean) * inv + b);
}

__global__ __launch_bounds__(256) void ln_kernel(
    const float* __restrict__ x, __nv_bfloat16* __restrict__ y,
    const float* __restrict__ alpha, const float* __restrict__ beta)
{
    ln_row(x, y, blockIdx.x, alpha, beta);
}

// ---------------- fused prep: LN1 (bids 0..S-1) + weight transposes (rest) ------
__global__ __launch_bounds__(256) void prep_kernel(
    const float* __restrict__ x, __nv_bfloat16* __restrict__ hb,
    const float* __restrict__ ln1a, const float* __restrict__ ln1b,
    const float* __restrict__ wq, const float* __restrict__ wk,
    const float* __restrict__ wv, const float* __restrict__ wo,
    const float* __restrict__ w1, const float* __restrict__ w2,
    __nv_bfloat16* __restrict__ wqt, __nv_bfloat16* __restrict__ wkt,
    __nv_bfloat16* __restrict__ wvt, __nv_bfloat16* __restrict__ wot,
    __nv_bfloat16* __restrict__ w1t, __nv_bfloat16* __restrict__ w2t)
{
    if (blockIdx.x < S) {
        ln_row(x, hb, blockIdx.x, ln1a, ln1b);
        return;
    }
    __shared__ float tile[32][33];
    int bid = blockIdx.x - S;
    const float* src; __nv_bfloat16* dst; int K, N, tl;
    if      (bid < 256)  { src = wq; dst = wqt; K = D;  N = D;  tl = bid; }
    else if (bid < 512)  { src = wk; dst = wkt; K = D;  N = D;  tl = bid - 256; }
    else if (bid < 768)  { src = wv; dst = wvt; K = D;  N = D;  tl = bid - 512; }
    else if (bid < 1024) { src = wo; dst = wot; K = D;  N = D;  tl = bid - 768; }
    else if (bid < 2048) { src = w1; dst = w1t; K = D;  N = FF; tl = bid - 1024; }
    else                 { src = w2; dst = w2t; K = FF; N = D;  tl = bid - 2048; }
    int tilesX = N / 32;
    int n0 = (tl % tilesX) * 32, k0 = (tl / tilesX) * 32;
    int tx = threadIdx.x & 31, ty = threadIdx.x >> 5;
    #pragma unroll
    for (int i = ty; i < 32; i += 8)
        tile[i][tx] = src[(size_t)(k0 + i) * N + n0 + tx];
    __syncthreads();
    #pragma unroll
    for (int i = ty; i < 32; i += 8)
        dst[(size_t)(n0 + i) * K + k0 + tx] = __float2bfloat16(tile[tx][i]);
}

// ---------------- bf16 mma GEMM: 3-stage cp.async ring + ldmatrix ----------------
// Tile: 128 x BN x 32. BN = 128 (8 warps 4x2, 32x64/warp) or 64 (32x32/warp).
#define GSTRW 20
#define GNST 3
#define G_TILE_A (128 * GSTRW)
#define G_STG_BN(BN)   (G_TILE_A + (BN) * GSTRW)
#define GEMM_SMEM_BN(BN) (GNST * G_STG_BN(BN) * 4)

template<int EPI, int OUTBF, int BN>
__global__ __launch_bounds__(256, 2) void gemm_bf(
    const __nv_bfloat16* __restrict__ A,
    const __nv_bfloat16* __restrict__ W0, const __nv_bfloat16* __restrict__ W1,
    const __nv_bfloat16* __restrict__ W2,
    const float* __restrict__ b0p, const float* __restrict__ b1p, const float* __restrict__ b2p,
    const float* __restrict__ R,
    void* __restrict__ C0v, void* __restrict__ C1v, void* __restrict__ C2v,
    int Ntot, int K)
{
    constexpr int NB = BN / 16;          // ni-blocks per warp
    constexpr int G_STG = G_STG_BN(BN);

    const __nv_bfloat16* W = blockIdx.z == 0 ? W0 : (blockIdx.z == 1 ? W1 : W2);
    const float* bias = blockIdx.z == 0 ? b0p : (blockIdx.z == 1 ? b1p : b2p);
    void* Cv          = blockIdx.z == 0 ? C0v : (blockIdx.z == 1 ? C1v : C2v);

    uint32_t* smw = (uint32_t*)sm_raw;
    uint32_t  smb = (uint32_t)__cvta_generic_to_shared(sm_raw);

    int tid  = threadIdx.x;
    int warp = tid >> 5, lane = tid & 31;
    int warp_m = warp >> 1, warp_n = warp & 1;
    int g = lane >> 2, t = lane & 3;

    int bm = blockIdx.y * 128;
    int bn = blockIdx.x * BN;
    int nk = K / 32;

    int srow = tid >> 2, sch = tid & 3;

    float acc[2][NB][4];
    #pragma unroll
    for (int mi = 0; mi < 2; mi++)
        #pragma unroll
        for (int ni = 0; ni < NB; ni++)
            #pragma unroll
            for (int r = 0; r < 4; r++) acc[mi][ni][r] = 0.f;

    auto stage = [&](int s, int k0) {
        uint32_t* As = smw + s * G_STG;
        uint32_t* Bs = As + G_TILE_A;
        #pragma unroll
        for (int it = 0; it < 2; it++) {
            int row = srow + 64 * it;
            cpa16(As + row * GSTRW + sch * 4, &A[(size_t)(bm + row) * K + k0 + sch * 8]);
        }
        #pragma unroll
        for (int it = 0; it < BN / 64; it++) {
            int row = srow + 64 * it;
            cpa16(Bs + row * GSTRW + sch * 4, &W[(size_t)(bn + row) * K + k0 + sch * 8]);
        }
    };

    stage(0, 0);
    CP_COMMIT();
    if (nk > 1) stage(1, 32);
    CP_COMMIT();

    int l16 = lane & 15, lhi = (lane >> 4) & 1;
    int l8 = lane & 7,  lmid = (lane >> 3) & 1;

    int s = 0;
    for (int i = 0; i < nk; i++, s = (s == GNST - 1) ? 0 : s + 1) {
        CP_WAIT1();
        __syncthreads();

        uint32_t abase = smb + (s * G_STG) * 4;
        uint32_t bbase = abase + G_TILE_A * 4;

        uint32_t a[2][4];
        ldsm_x4(a[0], abase + ((warp_m * 32 + l16) * GSTRW + lhi * 4) * 4);
        ldsm_x4(a[1], abase + ((warp_m * 32 + 16 + l16) * GSTRW + lhi * 4) * 4);

        if (i + 2 < nk) {
            int sn = s + 2; if (sn >= GNST) sn -= GNST;
            stage(sn, (i + 2) * 32);
        }
        CP_COMMIT();

        #pragma unroll
        for (int ni = 0; ni < NB; ni++) {
            uint32_t b0, b1;
            ldsm_x2(b0, b1, bbase + ((warp_n * (BN / 2) + ni * 8 + l8) * GSTRW + lmid * 4) * 4);
            mma_bf16(acc[0][ni], a[0], b0, b1);
            mma_bf16(acc[1][ni], a[1], b0, b1);
        }

        ldsm_x4(a[0], abase + ((warp_m * 32 + l16) * GSTRW + 8 + lhi * 4) * 4);
        ldsm_x4(a[1], abase + ((warp_m * 32 + 16 + l16) * GSTRW + 8 + lhi * 4) * 4);
        #pragma unroll
        for (int ni = 0; ni < NB; ni++) {
            uint32_t b0, b1;
            ldsm_x2(b0, b1, bbase + ((warp_n * (BN / 2) + ni * 8 + l8) * GSTRW + 8 + lmid * 4) * 4);
            mma_bf16(acc[0][ni], a[0], b0, b1);
            mma_bf16(acc[1][ni], a[1], b0, b1);
        }
    }

    // epilogue
    #pragma unroll
    for (int mi = 0; mi < 2; mi++) {
        int row0 = bm + warp_m * 32 + mi * 16 + g;
        #pragma unroll
        for (int ni = 0; ni < NB; ni++) {
            int col0 = bn + warp_n * (BN / 2) + ni * 8 + 2 * t;
            float b0 = bias[col0], b1 = bias[col0 + 1];
            float v0 = acc[mi][ni][0] + b0;
            float v1 = acc[mi][ni][1] + b1;
            float v2 = acc[mi][ni][2] + b0;
            float v3 = acc[mi][ni][3] + b1;
            if (EPI == 1) {
                v0 = fmaxf(v0, 0.f); v1 = fmaxf(v1, 0.f);
                v2 = fmaxf(v2, 0.f); v3 = fmaxf(v3, 0.f);
            }
            if (EPI == 2) {
                float2 r0 = *(const float2*)&R[(size_t)row0 * Ntot + col0];
                float2 r1 = *(const float2*)&R[(size_t)(row0 + 8) * Ntot + col0];
                v0 += r0.x; v1 += r0.y; v2 += r1.x; v3 += r1.y;
            }
            if (OUTBF) {
                __nv_bfloat16* C = (__nv_bfloat16*)Cv;
                *(uint32_t*)&C[(size_t)row0 * Ntot + col0]       = packbf(v0, v1);
                *(uint32_t*)&C[(size_t)(row0 + 8) * Ntot + col0] = packbf(v2, v3);
            } else {
                float* C = (float*)Cv;
                *(float2*)&C[(size_t)row0 * Ntot + col0]       = make_float2(v0, v1);
                *(float2*)&C[(size_t)(row0 + 8) * Ntot + col0] = make_float2(v2, v3);
            }
        }
    }
}

// ---------------- bf16 mma flash attention: static-max softmax + mma row-sums ----
#define ASTRW 36
#define NST 3
#define SMA_Q    0
#define SMA_K0   4608
#define SMA_V0   (SMA_K0 + NST * 64 * ASTRW)
#define SMA_M0   (SMA_V0 + NST * 64 * ASTRW)
#define ATTN_SMEM ((SMA_M0 + NST * 64) * 4)
#define SCALE_LOG2E 0.18033688011112042f
#define BF_ONE2 0x3F803F80u

__global__ __launch_bounds__(128, 2) void attn_bf(
    const __nv_bfloat16* __restrict__ Qb, const __nv_bfloat16* __restrict__ Kb,
    const __nv_bfloat16* __restrict__ Vb, const int* __restrict__ mask,
    __nv_bfloat16* __restrict__ O)
{
    uint32_t* sm = (uint32_t*)sm_raw;
    uint32_t  smb = (uint32_t)__cvta_generic_to_shared(sm_raw);
    uint32_t* Qs = sm + SMA_Q;

    int tid  = threadIdx.x;
    int warp = tid >> 5, lane = tid & 31;
    int g = lane >> 2, t = lane & 3;

    int hoff = blockIdx.y * DK;
    int q0   = blockIdx.x * 128;
    int wrow = warp * 32;

    for (int r = tid; r < NST * 64; r += 128) {
        uint4* p = (uint4*)(sm + SMA_V0 + r * ASTRW + 32);
        *p = make_uint4(BF_ONE2, BF_ONE2, BF_ONE2, BF_ONE2);
    }

    auto stage = [&](int s, int kt) {
        uint32_t* Ks = sm + SMA_K0 + s * 64 * ASTRW;
        uint32_t* Vs = sm + SMA_V0 + s * 64 * ASTRW;
        #pragma unroll
        for (int it = 0; it < 4; it++) {
            int slot = tid + it * 128;
            int row = slot >> 3, u4 = slot & 7;
            cpa16(Ks + row * ASTRW + u4 * 4, &Kb[(size_t)(kt + row) * D + hoff + u4 * 8]);
            cpa16(Vs + row * ASTRW + u4 * 4, &Vb[(size_t)(kt + row) * D + hoff + u4 * 8]);
        }
        if (tid < 16) cpa16(sm + SMA_M0 + s * 64 + tid * 4, &mask[kt + tid * 4]);
    };

    #pragma unroll
    for (int it = 0; it < 8; it++) {
        int slot = tid + it * 128;
        int row = slot >> 3, u4 = slot & 7;
        *(uint4*)(Qs + row * ASTRW + u4 * 4) =
            *(const uint4*)&Qb[(size_t)(q0 + row) * D + hoff + u4 * 8];
    }

    stage(0, 0);
    CP_COMMIT();
    stage(1, 64);
    CP_COMMIT();
    __syncthreads();

    uint32_t qf[2][4][4];
    #pragma unroll
    for (int mi = 0; mi < 2; mi++)
        #pragma unroll
        for (int c = 0; c < 4; c++) {
            int qidx = (wrow + mi * 16 + g) * ASTRW + c * 8 + t;
            qf[mi][c][0] = Qs[qidx];
            qf[mi][c][1] = Qs[qidx + 8 * ASTRW];
            qf[mi][c][2] = Qs[qidx + 4];
            qf[mi][c][3] = Qs[qidx + 8 * ASTRW + 4];
        }

    float o_[2][9][4];
    #pragma unroll
    for (int mi = 0; mi < 2; mi++)
        #pragma unroll
        for (int ni = 0; ni < 9; ni++)
            #pragma unroll
            for (int r = 0; r < 4; r++) o_[mi][ni][r] = 0.f;

    int klrow = ((lane >> 4) & 1) * 8 + (lane & 7);
    int klw   = ((lane >> 3) & 1) * 4;
    int vl16  = lane & 15;
    int vlw   = ((lane >> 4) & 1) * 4;

    const int NT = S / 64;
    int s = 0;
    for (int i = 0; i < NT; i++, s = (s == NST - 1) ? 0 : s + 1) {
        CP_WAIT1();
        __syncthreads();

        uint32_t kbase = smb + (SMA_K0 + s * 64 * ASTRW) * 4;
        uint32_t vbase = smb + (SMA_V0 + s * 64 * ASTRW) * 4;
        int*     Ms    = (int*)(sm + SMA_M0 + s * 64);

        float sc_[2][8][4];
        #pragma unroll
        for (int mi = 0; mi < 2; mi++)
            #pragma unroll
            for (int ni = 0; ni < 8; ni++)
                #pragma unroll
                for (int r = 0; r < 4; r++) sc_[mi][ni][r] = 0.f;

        #pragma unroll
        for (int c = 0; c < 4; c++) {
            #pragma unroll
            for (int np = 0; np < 4; np++) {
                uint32_t b[4];
                ldsm_x4(b, kbase + ((np * 16 + klrow) * ASTRW + c * 8 + klw) * 4);
                mma_bf16(sc_[0][2 * np],     qf[0][c], b[0], b[1]);
                mma_bf16(sc_[1][2 * np],     qf[1][c], b[0], b[1]);
                mma_bf16(sc_[0][2 * np + 1], qf[0][c], b[2], b[3]);
                mma_bf16(sc_[1][2 * np + 1], qf[1][c], b[2], b[3]);
            }
        }

        if (i + 2 < NT) {
            int sn = s + 2; if (sn >= NST) sn -= NST;
            stage(sn, (i + 2) * 64);
        }
        CP_COMMIT();

        float bs[8][2];
        #pragma unroll
        for (int ni = 0; ni < 8; ni++) {
            int col = ni * 8 + 2 * t;
            bs[ni][0] = Ms[col]     ? 0.f : -1e9f;
            bs[ni][1] = Ms[col + 1] ? 0.f : -1e9f;
        }

        #pragma unroll
        for (int mi = 0; mi < 2; mi++)
            #pragma unroll
            for (int ni = 0; ni < 8; ni++) {
                sc_[mi][ni][0] = ex2(fmaf(sc_[mi][ni][0], SCALE_LOG2E, bs[ni][0]));
                sc_[mi][ni][1] = ex2(fmaf(sc_[mi][ni][1], SCALE_LOG2E, bs[ni][1]));
                sc_[mi][ni][2] = ex2(fmaf(sc_[mi][ni][2], SCALE_LOG2E, bs[ni][0]));
                sc_[mi][ni][3] = ex2(fmaf(sc_[mi][ni][3], SCALE_LOG2E, bs[ni][1]));
            }

        #pragma unroll
        for (int c = 0; c < 4; c++) {
            uint32_t a0[4], a1[4];
            a0[0] = packbf(sc_[0][2 * c][0],     sc_[0][2 * c][1]);
            a0[1] = packbf(sc_[0][2 * c][2],     sc_[0][2 * c][3]);
            a0[2] = packbf(sc_[0][2 * c + 1][0], sc_[0][2 * c + 1][1]);
            a0[3] = packbf(sc_[0][2 * c + 1][2], sc_[0][2 * c + 1][3]);
            a1[0] = packbf(sc_[1][2 * c][0],     sc_[1][2 * c][1]);
            a1[1] = packbf(sc_[1][2 * c][2],     sc_[1][2 * c][3]);
            a1[2] = packbf(sc_[1][2 * c + 1][0], sc_[1][2 * c + 1][1]);
            a1[3] = packbf(sc_[1][2 * c + 1][2], sc_[1][2 * c + 1][3]);
            #pragma unroll
            for (int np = 0; np < 4; np++) {
                uint32_t v[4];
                ldsm_x4_t(v, vbase + ((c * 16 + vl16) * ASTRW + (2 * np) * 4 + vlw) * 4);
                mma_bf16(o_[0][2 * np],     a0, v[0], v[1]);
                mma_bf16(o_[1][2 * np],     a1, v[0], v[1]);
                mma_bf16(o_[0][2 * np + 1], a0, v[2], v[3]);
                mma_bf16(o_[1][2 * np + 1], a1, v[2], v[3]);
            }
            uint32_t w0, w1;
            ldsm_x2_t(w0, w1, vbase + ((c * 16 + vl16) * ASTRW + 32) * 4);
            mma_bf16(o_[0][8], a0, w0, w1);
            mma_bf16(o_[1][8], a1, w0, w1);
        }
    }

    #pragma unroll
    for (int mi = 0; mi < 2; mi++) {
        float inv_lo = 1.f / o_[mi][8][0];
        float inv_hi = 1.f / o_[mi][8][2];
        int row_lo = q0 + wrow + mi * 16 + g;
        int row_hi = row_lo + 8;
        #pragma unroll
        for (int ni = 0; ni < 8; ni++) {
            int col = hoff + ni * 8 + 2 * t;
            *(uint32_t*)&O[(size_t)row_lo * D + col] =
                packbf(o_[mi][ni][0] * inv_lo, o_[mi][ni][1] * inv_lo);
            *(uint32_t*)&O[(size_t)row_hi * D + col] =
                packbf(o_[mi][ni][2] * inv_hi, o_[mi][ni][3] * inv_hi);
        }
    }
}

// ---------------- launch ----------------
extern "C" void kernel_launch(void* const* d_in, const int* in_sizes, int n_in,
                              void* d_out, int out_size)
{
    const float* x    = (const float*)d_in[0];
    const int*   mask = (const int*)  d_in[1];
    const float* wq   = (const float*)d_in[2];
    const float* bq   = (const float*)d_in[3];
    const float* wk   = (const float*)d_in[4];
    const float* bk   = (const float*)d_in[5];
    const float* wv   = (const float*)d_in[6];
    const float* bv   = (const float*)d_in[7];
    const float* wo   = (const float*)d_in[8];
    const float* bo   = (const float*)d_in[9];
    const float* w1   = (const float*)d_in[10];
    const float* b1   = (const float*)d_in[11];
    const float* w2   = (const float*)d_in[12];
    const float* b2   = (const float*)d_in[13];
    const float* ln1a = (const float*)d_in[14];
    const float* ln1b = (const float*)d_in[15];
    const float* ln2a = (const float*)d_in[16];
    const float* ln2b = (const float*)d_in[17];
    float* out = (float*)d_out;

    float* x1;
    __nv_bfloat16 *hb, *h2b, *attnb, *ffb, *qb, *kb, *vb;
    __nv_bfloat16 *wqt, *wkt, *wvt, *wot, *w1t, *w2t;
    cudaGetSymbolAddress((void**)&x1,    g_x1);
    cudaGetSymbolAddress((void**)&hb,    g_hb);
    cudaGetSymbolAddress((void**)&h2b,   g_h2b);
    cudaGetSymbolAddress((void**)&attnb, g_attnb);
    cudaGetSymbolAddress((void**)&ffb,   g_ffb);
    cudaGetSymbolAddress((void**)&qb,    g_qb);
    cudaGetSymbolAddress((void**)&kb,    g_kb);
    cudaGetSymbolAddress((void**)&vb,    g_vb);
    cudaGetSymbolAddress((void**)&wqt,   g_wqt);
    cudaGetSymbolAddress((void**)&wkt,   g_wkt);
    cudaGetSymbolAddress((void**)&wvt,   g_wvt);
    cudaGetSymbolAddress((void**)&wot,   g_wot);
    cudaGetSymbolAddress((void**)&w1t,   g_w1t);
    cudaGetSymbolAddress((void**)&w2t,   g_w2t);

    cudaFuncSetAttribute(attn_bf, cudaFuncAttributeMaxDynamicSharedMemorySize, ATTN_SMEM);
    cudaFuncSetAttribute(gemm_bf<0, 1, 128>, cudaFuncAttributeMaxDynamicSharedMemorySize, GEMM_SMEM_BN(128));
    cudaFuncSetAttribute(gemm_bf<1, 1, 128>, cudaFuncAttributeMaxDynamicSharedMemorySize, GEMM_SMEM_BN(128));
    cudaFuncSetAttribute(gemm_bf<2, 0, 64>,  cudaFuncAttributeMaxDynamicSharedMemorySize, GEMM_SMEM_BN(64));

    // fused: LN1 + all weight transposes in one launch
    prep_kernel<<<S + 3072, 256>>>(x, hb, ln1a, ln1b,
                                   wq, wk, wv, wo, w1, w2,
                                   wqt, wkt, wvt, wot, w1t, w2t);

    // QKV fused -> bf16 outputs (384 CTAs)
    gemm_bf<0, 1, 128><<<dim3(D / 128, S / 128, 3), 256, GEMM_SMEM_BN(128)>>>(
        hb, wqt, wkt, wvt, bq, bk, bv, nullptr, qb, kb, vb, D, D);

    // attention -> bf16
    attn_bf<<<dim3(S / 128, H), 128, ATTN_SMEM>>>(qb, kb, vb, mask, attnb);

    // output projection + residual (fp32 x1) — BN=64 tiles, 256 CTAs
    gemm_bf<2, 0, 64><<<dim3(D / 64, S / 128, 1), 256, GEMM_SMEM_BN(64)>>>(
        attnb, wot, wot, wot, bo, bo, bo, x, x1, x1, x1, D, D);

    // LN2 -> bf16
    ln_kernel<<<S, 256>>>(x1, h2b, ln2a, ln2b);

    // FFN1 (512 CTAs)
    gemm_bf<1, 1, 128><<<dim3(FF / 128, S / 128, 1), 256, GEMM_SMEM_BN(128)>>>(
        h2b, w1t, w1t, w1t, b1, b1, b1, nullptr, ffb, ffb, ffb, FF, D);
    // FFN2 + residual -> out — BN=64 tiles, 256 CTAs
    gemm_bf<2, 0, 64><<<dim3(D / 64, S / 128, 1), 256, GEMM_SMEM_BN(64)>>>(
        ffb, w2t, w2t, w2t, b2, b2, b2, x1, out, out, out, D, FF);
}